// round 8
// baseline (speedup 1.0000x reference)
#include <cuda_runtime.h>
#include <cstdint>

#define B_ 4
#define N_ 2048
#define IND_ 256
#define H_ 4
#define D_ 64
#define HD_ 256
#define M_ (B_*N_)
#define NEG_SLOPE 0.2f
#define LOG2E 1.4426950408889634f

#define QTILE 128
#define JT 64
#define NCH (N_/JT)
#define NW (N_/32)      // bitmask words per row = 64

// Scratch (static __device__ arrays; no allocation allowed)
__device__ float g_hT[B_*H_*D_*N_];    // [bh][d][n], 8 MB
__device__ float g_srcT[B_*H_*N_];     // [bh][n]
__device__ float g_dstT[B_*H_*N_];
__device__ unsigned g_bm[N_*NW];       // bit-packed mask [q][w]
__device__ unsigned g_maxdst[B_*H_];

__global__ void k_init() {
    int t = threadIdx.x;
    if (t < B_*H_) g_maxdst[t] = 0u;
}

// ---------------------------------------------------------------------------
// helpers
// ---------------------------------------------------------------------------
__device__ __forceinline__ float ex2f(float x) {
    float r; asm("ex2.approx.f32 %0, %1;" : "=f"(r) : "f"(x)); return r;
}
__device__ __forceinline__ unsigned long long dupf(float v) {
    unsigned long long r;
    unsigned u = __float_as_uint(v);
    asm("mov.b64 %0, {%1, %1};" : "=l"(r) : "r"(u));
    return r;
}
#define FFMA2(d, a, b) asm("fma.rn.f32x2 %0, %1, %2, %0;" : "+l"(d) : "l"(a), "l"(b))

__device__ __forceinline__ uint32_t smem_u32(const void* p) {
    uint32_t a;
    asm("{ .reg .u64 tmp; cvta.to.shared.u64 tmp, %1; cvt.u32.u64 %0, tmp; }"
        : "=r"(a) : "l"(p));
    return a;
}
#define LDSM4(r0, r1, r2, r3, addr) \
    asm volatile("ldmatrix.sync.aligned.m8n8.x4.shared.b16 {%0,%1,%2,%3}, [%4];" \
                 : "=r"(r0), "=r"(r1), "=r"(r2), "=r"(r3) : "r"(addr))
#define MMA_TF32(d0, d1, d2, d3, a0, a1, a2, a3, b0, b1) \
    asm volatile("mma.sync.aligned.m16n8k8.row.col.f32.tf32.tf32.f32 " \
                 "{%0,%1,%2,%3}, {%4,%5,%6,%7}, {%8,%9}, {%0,%1,%2,%3};" \
                 : "+f"(d0), "+f"(d1), "+f"(d2), "+f"(d3) \
                 : "r"(a0), "r"(a1), "r"(a2), "r"(a3), "r"(b0), "r"(b1))

// ---------------------------------------------------------------------------
// Kernel: bit-pack the adjacency mask (16 reuses across b,h in k_attn)
// ---------------------------------------------------------------------------
__global__ __launch_bounds__(256) void k_bitpack(const int* __restrict__ A_mask) {
    int tid = blockIdx.x * 256 + threadIdx.x;          // 0 .. N_*NW-1
    const int4* p = (const int4*)(A_mask + tid * 32);  // row q = tid>>6, word w = tid&63
    unsigned bits = 0;
    #pragma unroll
    for (int i = 0; i < 8; i++) {
        int4 m = p[i];
        bits |= (unsigned)(m.x != 0) << (4*i)
             |  (unsigned)(m.y != 0) << (4*i+1)
             |  (unsigned)(m.z != 0) << (4*i+2)
             |  (unsigned)(m.w != 0) << (4*i+3);
    }
    g_bm[tid] = bits;
}

// ---------------------------------------------------------------------------
// Kernel 1: h = x @ W, FFMA2 micro-kernel, epilogue writes TRANSPOSED g_hT
// AND fused src/dst: each block holds (64 rows x one head's full 64 d), so
// it can produce g_srcT/g_dstT + per-(b,h) max directly (kills k_srcdst).
// ---------------------------------------------------------------------------
__global__ __launch_bounds__(256) void k_gemm(const float* __restrict__ x,
                                              const float* __restrict__ W,
                                              const float* __restrict__ a_src,
                                              const float* __restrict__ a_dst) {
    __shared__ float As[16][68];
    __shared__ float Bs[16][68];
    __shared__ float redS[64][17];
    __shared__ float redD[64][17];
    const int t  = threadIdx.x;
    const int m0 = blockIdx.x * 64;
    const int n0 = blockIdx.y * 64;       // head hh = n0>>6, d_local base = td*4
    const int tq = t >> 4, td = t & 15;
    const int am = t >> 2, ak4 = (t & 3) << 2;
    const int bk = t >> 4, bn4 = (t & 15) << 2;

    unsigned long long acc[4][2];
    #pragma unroll
    for (int i = 0; i < 4; i++) { acc[i][0] = 0ull; acc[i][1] = 0ull; }

    for (int k0 = 0; k0 < IND_; k0 += 16) {
        float4 av = *(const float4*)(x + (m0 + am) * IND_ + k0 + ak4);
        float4 bv = *(const float4*)(W + (k0 + bk) * HD_ + n0 + bn4);
        __syncthreads();
        As[ak4 + 0][am] = av.x;
        As[ak4 + 1][am] = av.y;
        As[ak4 + 2][am] = av.z;
        As[ak4 + 3][am] = av.w;
        *(float4*)&Bs[bk][bn4] = bv;
        __syncthreads();
        #pragma unroll
        for (int k = 0; k < 16; k++) {
            float a0[4];
            *(float4*)a0 = *(const float4*)&As[k][tq << 2];
            ulonglong2 bl = *(const ulonglong2*)&Bs[k][td << 2];
            #pragma unroll
            for (int i = 0; i < 4; i++) {
                unsigned long long ad = dupf(a0[i]);
                FFMA2(acc[i][0], ad, bl.x);
                FFMA2(acc[i][1], ad, bl.y);
            }
        }
    }
    // unpack accumulators: fm[i][dd] = h[m0+tq*4+i][n0 + td*4 + dd]
    float fm[4][4];
    #pragma unroll
    for (int i = 0; i < 4; i++) {
        unsigned lo, hi;
        asm("mov.b64 {%0, %1}, %2;" : "=r"(lo), "=r"(hi) : "l"(acc[i][0]));
        fm[i][0] = __uint_as_float(lo); fm[i][1] = __uint_as_float(hi);
        asm("mov.b64 {%0, %1}, %2;" : "=r"(lo), "=r"(hi) : "l"(acc[i][1]));
        fm[i][2] = __uint_as_float(lo); fm[i][3] = __uint_as_float(hi);
    }
    const int b  = m0 >> 11;
    const int nn = m0 & (N_ - 1);
    const int bh = b * H_ + (n0 >> 6);

    // transpose write: g_hT[bh][d][n]
    float* bp = g_hT + (bh * D_ + td * 4) * N_ + nn + tq * 4;
    #pragma unroll
    for (int dd = 0; dd < 4; dd++)
        *(float4*)(bp + dd * N_) = make_float4(fm[0][dd], fm[1][dd], fm[2][dd], fm[3][dd]);

    // fused src/dst partials: this thread covers d = td*4..+3 of head n0>>6
    {
        float sa4[4], sd4[4];
        #pragma unroll
        for (int dd = 0; dd < 4; dd++) {
            sa4[dd] = a_src[n0 + td * 4 + dd];
            sd4[dd] = a_dst[n0 + td * 4 + dd];
        }
        #pragma unroll
        for (int i = 0; i < 4; i++) {
            float ps = 0.f, pd = 0.f;
            #pragma unroll
            for (int dd = 0; dd < 4; dd++) {
                ps = fmaf(fm[i][dd], sa4[dd], ps);
                pd = fmaf(fm[i][dd], sd4[dd], pd);
            }
            redS[tq * 4 + i][td] = ps;
            redD[tq * 4 + i][td] = pd;
        }
    }
    __syncthreads();
    if (t < 64) {
        float s = 0.f, d = 0.f;
        #pragma unroll
        for (int j = 0; j < 16; j++) { s += redS[t][j]; d += redD[t][j]; }
        g_srcT[bh * N_ + nn + t] = s;
        g_dstT[bh * N_ + nn + t] = d;
        float mm = d;
        #pragma unroll
        for (int o = 16; o; o >>= 1)
            mm = fmaxf(mm, __shfl_xor_sync(0xffffffffu, mm, o));
        if ((t & 31) == 0) {
            unsigned bits = __float_as_uint(mm);
            unsigned enc  = (mm >= 0.f) ? (bits | 0x80000000u) : ~bits;
            atomicMax(&g_maxdst[bh], enc);
        }
    }
}

// ---------------------------------------------------------------------------
// Kernel 3: fused masked-softmax attention + AV on mma.sync tf32 (m16n8k8),
// DOUBLE-BUFFERED: stage chunk c+1 (LDG + exp + STS) while tensor pipe runs
// chunk c; one barrier per chunk. Pt[q][j] / Kt[d][j], 68-float row stride.
// ---------------------------------------------------------------------------
// smem float offsets
#define PT0_F   0                      // 128 x 68
#define PT1_F   8704
#define KT0_F   17408                  // 64 x 68
#define KT1_F   21760
#define SRC_F   26112
#define CL_F    26240
#define RED_F   26368
#define LS_F    26624
#define SM_TOTF 26752                  // floats = 107008 B
#define PT_DB   34816                  // byte delta between Pt buffers
#define KT_DB   17408                  // byte delta between Kt buffers

__global__ __launch_bounds__(256, 2) void k_attn(float* __restrict__ out) {
    extern __shared__ float sm[];
    float* sSrc = sm + SRC_F;
    float* sCl  = sm + CL_F;
    float* sRed = sm + RED_F;
    float* sLs  = sm + LS_F;

    const int t    = threadIdx.x;
    const int w    = t >> 5, lane = t & 31;
    const int qt0  = blockIdx.x * QTILE;
    const int bh   = blockIdx.y;
    const int b    = bh >> 2, hh = bh & 3;
    const int rowbase = b * N_;

    unsigned enc = g_maxdst[bh];
    float mdst = (enc & 0x80000000u) ? __uint_as_float(enc & 0x7fffffffu)
                                     : __uint_as_float(~enc);
    if (t < QTILE) {
        float s = g_srcT[bh * N_ + qt0 + t];
        sSrc[t] = s;
        float l = s + mdst;
        float C = fmaxf(l, NEG_SLOPE * l);
        sCl[t] = C * LOG2E;
    }
    __syncthreads();

    // ---- staging mappings ----
    const int pq   = t & 127;              // P-gen: q row
    const int half = t >> 7;               // j range half*32..+31
    const float sv = sSrc[pq];
    const float Cl = sCl[pq];
    const int prow_off = pq * 68 + half * 32;           // into Pt buffer (floats)
    const int kd   = t >> 2;               // Kt: d row
    const int kj16 = (t & 3) << 4;
    const int krow_off = kd * 68 + kj16;                // into Kt buffer (floats)
    const float* ksrc0 = g_hT + (bh * D_ + kd) * N_ + kj16;

    // ---- ldmatrix lane addresses (byte, buffer 0) ----
    const uint32_t smb = smem_u32(sm);
    const int lm = lane >> 3, lr = lane & 7;
    const int q0 = w * 16;
    const uint32_t aaddr0 = smb + (uint32_t)(((q0 + lr + ((lm & 1) << 3)) * 68
                                              + ((lm >> 1) << 2)) << 2);
    uint32_t baddr0[4];
    #pragma unroll
    for (int p = 0; p < 4; p++) {
        int nt = p + ((lm >> 1) << 2);
        baddr0[p] = smb + (uint32_t)((KT0_F + (nt * 8 + lr) * 68
                                      + ((lm & 1) << 2)) << 2);
    }

    float acc[8][4];
    #pragma unroll
    for (int n = 0; n < 8; n++)
        #pragma unroll
        for (int i = 0; i < 4; i++) acc[n][i] = 0.f;
    float lsum = 0.f;

#define STAGE(j0, kbuf, pbuf)                                                 \
    {                                                                         \
        const float* ks = ksrc0 + (j0);                                       \
        float* krow = (kbuf) + krow_off;                                      \
        _Pragma("unroll")                                                     \
        for (int i = 0; i < 4; i++)                                           \
            *(float4*)(krow + (i << 2)) = *(const float4*)(ks + (i << 2));    \
        unsigned mw = g_bm[(qt0 + pq) * NW + ((j0) >> 5) + half];             \
        const float* dp = g_dstT + bh * N_ + (j0) + (half << 5);              \
        float* prow = (pbuf) + prow_off;                                      \
        _Pragma("unroll")                                                     \
        for (int g = 0; g < 8; g++) {                                         \
            float4 dv = *(const float4*)(dp + (g << 2));                      \
            float l0 = sv + dv.x, l1 = sv + dv.y, l2 = sv + dv.z, l3 = sv + dv.w; \
            l0 = fmaxf(l0, NEG_SLOPE * l0);                                   \
            l1 = fmaxf(l1, NEG_SLOPE * l1);                                   \
            l2 = fmaxf(l2, NEG_SLOPE * l2);                                   \
            l3 = fmaxf(l3, NEG_SLOPE * l3);                                   \
            float e0 = ex2f(fmaf(l0, LOG2E, -Cl));                            \
            float e1 = ex2f(fmaf(l1, LOG2E, -Cl));                            \
            float e2 = ex2f(fmaf(l2, LOG2E, -Cl));                            \
            float e3 = ex2f(fmaf(l3, LOG2E, -Cl));                            \
            unsigned mb = mw >> (g * 4);                                      \
            e0 = (mb & 1u) ? e0 : 0.f;                                        \
            e1 = (mb & 2u) ? e1 : 0.f;                                        \
            e2 = (mb & 4u) ? e2 : 0.f;                                        \
            e3 = (mb & 8u) ? e3 : 0.f;                                        \
            lsum += (e0 + e1) + (e2 + e3);                                    \
            *(float4*)(prow + (g << 2)) = make_float4(e0, e1, e2, e3);        \
        }                                                                     \
    }

    // prologue: stage chunk 0 into buffer 0
    STAGE(0, sm + KT0_F, sm + PT0_F);

    for (int c = 0; c < NCH; c++) {
        const int sel = c & 1;
        __syncthreads();
        if (c < NCH - 1) {
            if (sel) STAGE((c + 1) * JT, sm + KT0_F, sm + PT0_F)
            else     STAGE((c + 1) * JT, sm + KT1_F, sm + PT1_F)
        }
        // ---- GEMM on buffer sel: 8 k-steps of m16n8k8 tf32, 8 n-tiles ----
        const uint32_t aa = aaddr0 + (uint32_t)(sel * PT_DB);
        const uint32_t bdlt = (uint32_t)(sel * KT_DB);
        #pragma unroll
        for (int k = 0; k < 8; k++) {
            uint32_t a0, a1, a2, a3;
            LDSM4(a0, a1, a2, a3, aa + (k << 5));
            #pragma unroll
            for (int p = 0; p < 4; p++) {
                uint32_t b0, b1, b2, b3;
                LDSM4(b0, b1, b2, b3, baddr0[p] + bdlt + (k << 5));
                MMA_TF32(acc[p][0], acc[p][1], acc[p][2], acc[p][3],
                         a0, a1, a2, a3, b0, b1);
                MMA_TF32(acc[p + 4][0], acc[p + 4][1], acc[p + 4][2], acc[p + 4][3],
                         a0, a1, a2, a3, b2, b3);
            }
        }
    }
#undef STAGE

    // ---- lsum combine across the two half-threads per q ----
    sRed[t] = lsum;
    __syncthreads();
    if (t < QTILE) sLs[t] = sRed[t] + sRed[t + QTILE];
    __syncthreads();

    // ---- epilogue: normalize + ELU + store from fragments ----
    {
        const int g  = lane >> 2;
        const int tc = (lane & 3) << 1;
        const int qa = q0 + g, qb = q0 + g + 8;
        const float inva = 1.f / sLs[qa];
        const float invb = 1.f / sLs[qb];
        float* opa = out + (rowbase + qt0 + qa) * HD_ + hh * D_ + tc;
        float* opb = out + (rowbase + qt0 + qb) * HD_ + hh * D_ + tc;
        #pragma unroll
        for (int nt = 0; nt < 8; nt++) {
            float v0 = acc[nt][0] * inva;
            float v1 = acc[nt][1] * inva;
            float v2 = acc[nt][2] * invb;
            float v3 = acc[nt][3] * invb;
            v0 = (v0 > 0.f) ? v0 : expm1f(v0);
            v1 = (v1 > 0.f) ? v1 : expm1f(v1);
            v2 = (v2 > 0.f) ? v2 : expm1f(v2);
            v3 = (v3 > 0.f) ? v3 : expm1f(v3);
            *(float2*)(opa + nt * 8) = make_float2(v0, v1);
            *(float2*)(opb + nt * 8) = make_float2(v2, v3);
        }
    }
}

// ---------------------------------------------------------------------------
extern "C" void kernel_launch(void* const* d_in, const int* in_sizes, int n_in,
                              void* d_out, int out_size) {
    const float* x      = (const float*)d_in[0];
    const int*   A_mask = (const int*)d_in[1];
    const float* W      = (const float*)d_in[2];
    const float* a_src  = (const float*)d_in[3];
    const float* a_dst  = (const float*)d_in[4];
    float* out = (float*)d_out;

    cudaFuncSetAttribute(k_attn, cudaFuncAttributeMaxDynamicSharedMemorySize,
                         SM_TOTF * (int)sizeof(float));

    k_init<<<1, 32>>>();
    k_bitpack<<<(N_ * NW) / 256, 256>>>(A_mask);
    k_gemm<<<dim3(M_ / 64, HD_ / 64), 256>>>(x, W, a_src, a_dst);
    k_attn<<<dim3(N_ / QTILE, B_ * H_), 256, SM_TOTF * (int)sizeof(float)>>>(out);
}

// round 9
// speedup vs baseline: 1.1187x; 1.1187x over previous
#include <cuda_runtime.h>
#include <cstdint>

#define B_ 4
#define N_ 2048
#define IND_ 256
#define H_ 4
#define D_ 64
#define HD_ 256
#define M_ (B_*N_)
#define NEG_SLOPE 0.2f
#define LOG2E 1.4426950408889634f

#define QTILE 128
#define JT 64
#define NCH (N_/JT)
#define NW (N_/32)      // bitmask words per row = 64

// Scratch (static __device__ arrays; no allocation allowed)
__device__ float g_hT[B_*H_*D_*N_];    // [bh][d][n], 8 MB
__device__ float g_srcT[B_*H_*N_];     // [bh][n]
__device__ float g_dstT[B_*H_*N_];
__device__ unsigned g_bm[NW*N_];       // bit-packed mask TRANSPOSED [w][q]
__device__ unsigned g_maxdst[B_*H_];

__global__ void k_init() {
    int t = threadIdx.x;
    if (t < B_*H_) g_maxdst[t] = 0u;
}

// ---------------------------------------------------------------------------
// helpers
// ---------------------------------------------------------------------------
__device__ __forceinline__ float ex2f(float x) {
    float r; asm("ex2.approx.f32 %0, %1;" : "=f"(r) : "f"(x)); return r;
}
__device__ __forceinline__ unsigned long long dupf(float v) {
    unsigned long long r;
    unsigned u = __float_as_uint(v);
    asm("mov.b64 %0, {%1, %1};" : "=l"(r) : "r"(u));
    return r;
}
#define FFMA2(d, a, b) asm("fma.rn.f32x2 %0, %1, %2, %0;" : "+l"(d) : "l"(a), "l"(b))

__device__ __forceinline__ uint32_t smem_u32(const void* p) {
    uint32_t a;
    asm("{ .reg .u64 tmp; cvta.to.shared.u64 tmp, %1; cvt.u32.u64 %0, tmp; }"
        : "=r"(a) : "l"(p));
    return a;
}
#define LDSM4(r0, r1, r2, r3, addr) \
    asm volatile("ldmatrix.sync.aligned.m8n8.x4.shared.b16 {%0,%1,%2,%3}, [%4];" \
                 : "=r"(r0), "=r"(r1), "=r"(r2), "=r"(r3) : "r"(addr))
#define MMA_TF32(d0, d1, d2, d3, a0, a1, a2, a3, b0, b1) \
    asm volatile("mma.sync.aligned.m16n8k8.row.col.f32.tf32.tf32.f32 " \
                 "{%0,%1,%2,%3}, {%4,%5,%6,%7}, {%8,%9}, {%0,%1,%2,%3};" \
                 : "+f"(d0), "+f"(d1), "+f"(d2), "+f"(d3) \
                 : "r"(a0), "r"(a1), "r"(a2), "r"(a3), "r"(b0), "r"(b1))

// ---------------------------------------------------------------------------
// Kernel: bit-pack the adjacency mask, TRANSPOSED g_bm[w][q] so k_attn's
// per-chunk mask staging is coalesced along q.
// ---------------------------------------------------------------------------
__global__ __launch_bounds__(256) void k_bitpack(const int* __restrict__ A_mask) {
    int tid = blockIdx.x * 256 + threadIdx.x;   // 0 .. N_*NW-1
    int q = tid & (N_ - 1);
    int w = tid >> 11;
    const int4* p = (const int4*)(A_mask + q * N_ + w * 32);
    unsigned bits = 0;
    #pragma unroll
    for (int i = 0; i < 8; i++) {
        int4 m = p[i];
        bits |= (unsigned)(m.x != 0) << (4*i)
             |  (unsigned)(m.y != 0) << (4*i+1)
             |  (unsigned)(m.z != 0) << (4*i+2)
             |  (unsigned)(m.w != 0) << (4*i+3);
    }
    g_bm[w * N_ + q] = bits;
}

// ---------------------------------------------------------------------------
// Kernel 1: h = x @ W, FFMA2 micro-kernel; epilogue writes TRANSPOSED g_hT
// and fused src/dst (+ per-(b,h) max) — each block holds 64 rows x one head.
// ---------------------------------------------------------------------------
__global__ __launch_bounds__(256) void k_gemm(const float* __restrict__ x,
                                              const float* __restrict__ W,
                                              const float* __restrict__ a_src,
                                              const float* __restrict__ a_dst) {
    __shared__ float As[16][68];
    __shared__ float Bs[16][68];
    __shared__ float redS[64][17];
    __shared__ float redD[64][17];
    const int t  = threadIdx.x;
    const int m0 = blockIdx.x * 64;
    const int n0 = blockIdx.y * 64;
    const int tq = t >> 4, td = t & 15;
    const int am = t >> 2, ak4 = (t & 3) << 2;
    const int bk = t >> 4, bn4 = (t & 15) << 2;

    unsigned long long acc[4][2];
    #pragma unroll
    for (int i = 0; i < 4; i++) { acc[i][0] = 0ull; acc[i][1] = 0ull; }

    for (int k0 = 0; k0 < IND_; k0 += 16) {
        float4 av = *(const float4*)(x + (m0 + am) * IND_ + k0 + ak4);
        float4 bv = *(const float4*)(W + (k0 + bk) * HD_ + n0 + bn4);
        __syncthreads();
        As[ak4 + 0][am] = av.x;
        As[ak4 + 1][am] = av.y;
        As[ak4 + 2][am] = av.z;
        As[ak4 + 3][am] = av.w;
        *(float4*)&Bs[bk][bn4] = bv;
        __syncthreads();
        #pragma unroll
        for (int k = 0; k < 16; k++) {
            float a0[4];
            *(float4*)a0 = *(const float4*)&As[k][tq << 2];
            ulonglong2 bl = *(const ulonglong2*)&Bs[k][td << 2];
            #pragma unroll
            for (int i = 0; i < 4; i++) {
                unsigned long long ad = dupf(a0[i]);
                FFMA2(acc[i][0], ad, bl.x);
                FFMA2(acc[i][1], ad, bl.y);
            }
        }
    }
    float fm[4][4];
    #pragma unroll
    for (int i = 0; i < 4; i++) {
        unsigned lo, hi;
        asm("mov.b64 {%0, %1}, %2;" : "=r"(lo), "=r"(hi) : "l"(acc[i][0]));
        fm[i][0] = __uint_as_float(lo); fm[i][1] = __uint_as_float(hi);
        asm("mov.b64 {%0, %1}, %2;" : "=r"(lo), "=r"(hi) : "l"(acc[i][1]));
        fm[i][2] = __uint_as_float(lo); fm[i][3] = __uint_as_float(hi);
    }
    const int b  = m0 >> 11;
    const int nn = m0 & (N_ - 1);
    const int bh = b * H_ + (n0 >> 6);

    float* bp = g_hT + (bh * D_ + td * 4) * N_ + nn + tq * 4;
    #pragma unroll
    for (int dd = 0; dd < 4; dd++)
        *(float4*)(bp + dd * N_) = make_float4(fm[0][dd], fm[1][dd], fm[2][dd], fm[3][dd]);

    {
        float sa4[4], sd4[4];
        #pragma unroll
        for (int dd = 0; dd < 4; dd++) {
            sa4[dd] = a_src[n0 + td * 4 + dd];
            sd4[dd] = a_dst[n0 + td * 4 + dd];
        }
        #pragma unroll
        for (int i = 0; i < 4; i++) {
            float ps = 0.f, pd = 0.f;
            #pragma unroll
            for (int dd = 0; dd < 4; dd++) {
                ps = fmaf(fm[i][dd], sa4[dd], ps);
                pd = fmaf(fm[i][dd], sd4[dd], pd);
            }
            redS[tq * 4 + i][td] = ps;
            redD[tq * 4 + i][td] = pd;
        }
    }
    __syncthreads();
    if (t < 64) {
        float s = 0.f, d = 0.f;
        #pragma unroll
        for (int j = 0; j < 16; j++) { s += redS[t][j]; d += redD[t][j]; }
        g_srcT[bh * N_ + nn + t] = s;
        g_dstT[bh * N_ + nn + t] = d;
        float mm = d;
        #pragma unroll
        for (int o = 16; o; o >>= 1)
            mm = fmaxf(mm, __shfl_xor_sync(0xffffffffu, mm, o));
        if ((t & 31) == 0) {
            unsigned bits = __float_as_uint(mm);
            unsigned enc  = (mm >= 0.f) ? (bits | 0x80000000u) : ~bits;
            atomicMax(&g_maxdst[bh], enc);
        }
    }
}

// ---------------------------------------------------------------------------
// Kernel 3: fused masked-softmax attention + AV, mma.sync tf32 (m16n8k8).
// A-fragments (P values) computed DIRECTLY IN REGISTERS per the tf32 frag
// lane mapping — no Pt smem tile, no P STS, no A ldmatrix. Only Kt (B) is
// staged in smem (double-buffered) + per-chunk dst/mask tiles.
// ---------------------------------------------------------------------------
// smem float offsets
#define KT0_F   0                      // 64 x 68
#define KT1_F   4352
#define SDST_F  8704                   // 2 x 64
#define SBM_F   8832                   // 2 x 256 (unsigned)
#define SRC_F   9344
#define CL_F    9472
#define LS_F    9600
#define SM_TOTF 9728                   // floats = 38912 B
#define KT_DB   17408                  // byte delta between Kt buffers

__global__ __launch_bounds__(256, 3) void k_attn(float* __restrict__ out) {
    extern __shared__ float sm[];
    float*    sDst = sm + SDST_F;
    unsigned* sBm  = (unsigned*)(sm + SBM_F);
    float*    sSrc = sm + SRC_F;
    float*    sCl  = sm + CL_F;
    float*    sLs  = sm + LS_F;

    const int t    = threadIdx.x;
    const int w    = t >> 5, lane = t & 31;
    const int qt0  = blockIdx.x * QTILE;
    const int bh   = blockIdx.y;
    const int b    = bh >> 2, hh = bh & 3;
    const int rowbase = b * N_;

    unsigned enc = g_maxdst[bh];
    float mdst = (enc & 0x80000000u) ? __uint_as_float(enc & 0x7fffffffu)
                                     : __uint_as_float(~enc);
    if (t < QTILE) {
        float s = g_srcT[bh * N_ + qt0 + t];
        sSrc[t] = s;
        float l = s + mdst;
        float C = fmaxf(l, NEG_SLOPE * l);
        sCl[t] = C * LOG2E;
    }

    // ---- Kt staging mapping: d = t>>2, 16 j per thread ----
    const int kd   = t >> 2;
    const int kj16 = (t & 3) << 4;
    const int krow_off = kd * 68 + kj16;
    const float* ksrc0 = g_hT + (bh * D_ + kd) * N_ + kj16;

    // ---- fragment lane mapping ----
    const int g  = lane >> 2;       // 0..7
    const int lc = lane & 3;        // 0..3
    const int qa = w * 16 + g, qb = qa + 8;

    // ---- ldmatrix B lane addresses (byte, buffer 0) ----
    const uint32_t smb = smem_u32(sm);
    const int lm = lane >> 3, lr = lane & 7;
    uint32_t baddr0[4];
    #pragma unroll
    for (int p = 0; p < 4; p++) {
        int nt = p + ((lm >> 1) << 2);
        baddr0[p] = smb + (uint32_t)((KT0_F + (nt * 8 + lr) * 68
                                      + ((lm & 1) << 2)) << 2);
    }

    __syncthreads();
    const float sva = sSrc[qa], Cla = sCl[qa];
    const float svb = sSrc[qb], Clb = sCl[qb];

    float acc[8][4];
    #pragma unroll
    for (int n = 0; n < 8; n++)
        #pragma unroll
        for (int i = 0; i < 4; i++) acc[n][i] = 0.f;
    float lsA = 0.f, lsB = 0.f;

#define STAGE(j0, s)                                                          \
    {                                                                         \
        float* krow = sm + ((s) ? KT1_F : KT0_F) + krow_off;                  \
        const float* ks = ksrc0 + (j0);                                       \
        _Pragma("unroll")                                                     \
        for (int i = 0; i < 4; i++)                                           \
            *(float4*)(krow + (i << 2)) = *(const float4*)(ks + (i << 2));    \
        if (t < JT) sDst[(s) * 64 + t] = g_dstT[bh * N_ + (j0) + t];          \
        sBm[(s) * 256 + t] =                                                  \
            g_bm[(((j0) >> 5) + (t >> 7)) * N_ + qt0 + (t & 127)];            \
    }

    STAGE(0, 0);

    for (int ch = 0; ch < NCH; ch++) {
        const int sel = ch & 1;
        __syncthreads();
        if (ch < NCH - 1) {
            if (sel) STAGE((ch + 1) * JT, 0)
            else     STAGE((ch + 1) * JT, 1)
        }
        const float*    sD = sDst + sel * 64;
        const unsigned* sB = sBm + sel * 256;
        const unsigned long long bmA =
            ((unsigned long long)sB[128 + qa] << 32) | sB[qa];
        const unsigned long long bmB =
            ((unsigned long long)sB[128 + qb] << 32) | sB[qb];
        const uint32_t bdlt = (uint32_t)(sel * KT_DB);

        #pragma unroll
        for (int k = 0; k < 8; k++) {
            const int j1 = (k << 3) + lc;
            const int j2 = j1 + 4;
            float d1 = sD[j1], d2 = sD[j2];
            // A fragment: a0=P[qa][j1] a1=P[qb][j1] a2=P[qa][j2] a3=P[qb][j2]
            float l0 = sva + d1, l1 = svb + d1, l2 = sva + d2, l3 = svb + d2;
            l0 = fmaxf(l0, NEG_SLOPE * l0);
            l1 = fmaxf(l1, NEG_SLOPE * l1);
            l2 = fmaxf(l2, NEG_SLOPE * l2);
            l3 = fmaxf(l3, NEG_SLOPE * l3);
            float e0 = ex2f(fmaf(l0, LOG2E, -Cla));
            float e1 = ex2f(fmaf(l1, LOG2E, -Clb));
            float e2 = ex2f(fmaf(l2, LOG2E, -Cla));
            float e3 = ex2f(fmaf(l3, LOG2E, -Clb));
            e0 = ((bmA >> j1) & 1ull) ? e0 : 0.f;
            e1 = ((bmB >> j1) & 1ull) ? e1 : 0.f;
            e2 = ((bmA >> j2) & 1ull) ? e2 : 0.f;
            e3 = ((bmB >> j2) & 1ull) ? e3 : 0.f;
            lsA += e0 + e2;
            lsB += e1 + e3;
            const uint32_t a0 = __float_as_uint(e0);
            const uint32_t a1 = __float_as_uint(e1);
            const uint32_t a2 = __float_as_uint(e2);
            const uint32_t a3 = __float_as_uint(e3);
            #pragma unroll
            for (int p = 0; p < 4; p++) {
                uint32_t b0, b1, b2, b3;
                LDSM4(b0, b1, b2, b3, baddr0[p] + bdlt + (k << 5));
                MMA_TF32(acc[p][0], acc[p][1], acc[p][2], acc[p][3],
                         a0, a1, a2, a3, b0, b1);
                MMA_TF32(acc[p + 4][0], acc[p + 4][1], acc[p + 4][2], acc[p + 4][3],
                         a0, a1, a2, a3, b2, b3);
            }
        }
    }
#undef STAGE

    // ---- lsum: reduce across the 4 lanes (lc) sharing each q-row ----
    lsA += __shfl_xor_sync(0xffffffffu, lsA, 1);
    lsA += __shfl_xor_sync(0xffffffffu, lsA, 2);
    lsB += __shfl_xor_sync(0xffffffffu, lsB, 1);
    lsB += __shfl_xor_sync(0xffffffffu, lsB, 2);
    if (lc == 0) { sLs[qa] = lsA; sLs[qb] = lsB; }
    __syncthreads();

    // ---- epilogue: normalize + ELU + store from fragments ----
    {
        const int tc = lc << 1;
        const float inva = 1.f / sLs[qa];
        const float invb = 1.f / sLs[qb];
        float* opa = out + (rowbase + qt0 + qa) * HD_ + hh * D_ + tc;
        float* opb = out + (rowbase + qt0 + qb) * HD_ + hh * D_ + tc;
        #pragma unroll
        for (int nt = 0; nt < 8; nt++) {
            float v0 = acc[nt][0] * inva;
            float v1 = acc[nt][1] * inva;
            float v2 = acc[nt][2] * invb;
            float v3 = acc[nt][3] * invb;
            v0 = (v0 > 0.f) ? v0 : expm1f(v0);
            v1 = (v1 > 0.f) ? v1 : expm1f(v1);
            v2 = (v2 > 0.f) ? v2 : expm1f(v2);
            v3 = (v3 > 0.f) ? v3 : expm1f(v3);
            *(float2*)(opa + nt * 8) = make_float2(v0, v1);
            *(float2*)(opb + nt * 8) = make_float2(v2, v3);
        }
    }
}

// ---------------------------------------------------------------------------
extern "C" void kernel_launch(void* const* d_in, const int* in_sizes, int n_in,
                              void* d_out, int out_size) {
    const float* x      = (const float*)d_in[0];
    const int*   A_mask = (const int*)d_in[1];
    const float* W      = (const float*)d_in[2];
    const float* a_src  = (const float*)d_in[3];
    const float* a_dst  = (const float*)d_in[4];
    float* out = (float*)d_out;

    cudaFuncSetAttribute(k_attn, cudaFuncAttributeMaxDynamicSharedMemorySize,
                         SM_TOTF * (int)sizeof(float));

    k_init<<<1, 32>>>();
    k_bitpack<<<(N_ * NW) / 256, 256>>>(A_mask);
    k_gemm<<<dim3(M_ / 64, HD_ / 64), 256>>>(x, W, a_src, a_dst);
    k_attn<<<dim3(N_ / QTILE, B_ * H_), 256, SM_TOTF * (int)sizeof(float)>>>(out);
}

// round 10
// speedup vs baseline: 1.1333x; 1.0130x over previous
#include <cuda_runtime.h>
#include <cstdint>

#define B_ 4
#define N_ 2048
#define IND_ 256
#define H_ 4
#define D_ 64
#define HD_ 256
#define M_ (B_*N_)
#define NEG_SLOPE 0.2f
#define LOG2E 1.4426950408889634f

#define QTILE 128
#define JT 64
#define JSPLIT 2
#define JRANGE (N_/JSPLIT)          // 1024 j per block
#define NCHB (JRANGE/JT)            // 16 chunks per block
#define NW (N_/32)                  // bitmask words per row = 64

// Scratch (static __device__ arrays; no allocation allowed)
__device__ float g_hT[B_*H_*D_*N_];    // [bh][d][n], 8 MB
__device__ float g_srcT[B_*H_*N_];     // [bh][n]
__device__ float g_dstT[B_*H_*N_];
__device__ unsigned g_bm[NW*N_];       // bit-packed mask TRANSPOSED [w][q]
__device__ unsigned g_maxdst[B_*H_];
__device__ float g_pout[JSPLIT*B_*H_*N_*D_];   // 16 MB partial AV
__device__ float g_plsum[JSPLIT*B_*H_*N_];     // partial lsum

__global__ void k_init() {
    int t = threadIdx.x;
    if (t < B_*H_) g_maxdst[t] = 0u;
}

// ---------------------------------------------------------------------------
// helpers
// ---------------------------------------------------------------------------
__device__ __forceinline__ float ex2f(float x) {
    float r; asm("ex2.approx.f32 %0, %1;" : "=f"(r) : "f"(x)); return r;
}
__device__ __forceinline__ unsigned long long dupf(float v) {
    unsigned long long r;
    unsigned u = __float_as_uint(v);
    asm("mov.b64 %0, {%1, %1};" : "=l"(r) : "r"(u));
    return r;
}
#define FFMA2(d, a, b) asm("fma.rn.f32x2 %0, %1, %2, %0;" : "+l"(d) : "l"(a), "l"(b))

__device__ __forceinline__ uint32_t smem_u32(const void* p) {
    uint32_t a;
    asm("{ .reg .u64 tmp; cvta.to.shared.u64 tmp, %1; cvt.u32.u64 %0, tmp; }"
        : "=r"(a) : "l"(p));
    return a;
}
#define LDSM4(r0, r1, r2, r3, addr) \
    asm volatile("ldmatrix.sync.aligned.m8n8.x4.shared.b16 {%0,%1,%2,%3}, [%4];" \
                 : "=r"(r0), "=r"(r1), "=r"(r2), "=r"(r3) : "r"(addr))
#define MMA_TF32(d0, d1, d2, d3, a0, a1, a2, a3, b0, b1) \
    asm volatile("mma.sync.aligned.m16n8k8.row.col.f32.tf32.tf32.f32 " \
                 "{%0,%1,%2,%3}, {%4,%5,%6,%7}, {%8,%9}, {%0,%1,%2,%3};" \
                 : "+f"(d0), "+f"(d1), "+f"(d2), "+f"(d3) \
                 : "r"(a0), "r"(a1), "r"(a2), "r"(a3), "r"(b0), "r"(b1))

// ---------------------------------------------------------------------------
// Kernel: bit-pack the adjacency mask, TRANSPOSED g_bm[w][q]
// ---------------------------------------------------------------------------
__global__ __launch_bounds__(256) void k_bitpack(const int* __restrict__ A_mask) {
    int tid = blockIdx.x * 256 + threadIdx.x;
    int q = tid & (N_ - 1);
    int w = tid >> 11;
    const int4* p = (const int4*)(A_mask + q * N_ + w * 32);
    unsigned bits = 0;
    #pragma unroll
    for (int i = 0; i < 8; i++) {
        int4 m = p[i];
        bits |= (unsigned)(m.x != 0) << (4*i)
             |  (unsigned)(m.y != 0) << (4*i+1)
             |  (unsigned)(m.z != 0) << (4*i+2)
             |  (unsigned)(m.w != 0) << (4*i+3);
    }
    g_bm[w * N_ + q] = bits;
}

// ---------------------------------------------------------------------------
// Kernel 1: h = x @ W, FFMA2; epilogue writes TRANSPOSED g_hT + fused src/dst
// ---------------------------------------------------------------------------
__global__ __launch_bounds__(256) void k_gemm(const float* __restrict__ x,
                                              const float* __restrict__ W,
                                              const float* __restrict__ a_src,
                                              const float* __restrict__ a_dst) {
    __shared__ float As[16][68];
    __shared__ float Bs[16][68];
    __shared__ float redS[64][17];
    __shared__ float redD[64][17];
    const int t  = threadIdx.x;
    const int m0 = blockIdx.x * 64;
    const int n0 = blockIdx.y * 64;
    const int tq = t >> 4, td = t & 15;
    const int am = t >> 2, ak4 = (t & 3) << 2;
    const int bk = t >> 4, bn4 = (t & 15) << 2;

    unsigned long long acc[4][2];
    #pragma unroll
    for (int i = 0; i < 4; i++) { acc[i][0] = 0ull; acc[i][1] = 0ull; }

    for (int k0 = 0; k0 < IND_; k0 += 16) {
        float4 av = *(const float4*)(x + (m0 + am) * IND_ + k0 + ak4);
        float4 bv = *(const float4*)(W + (k0 + bk) * HD_ + n0 + bn4);
        __syncthreads();
        As[ak4 + 0][am] = av.x;
        As[ak4 + 1][am] = av.y;
        As[ak4 + 2][am] = av.z;
        As[ak4 + 3][am] = av.w;
        *(float4*)&Bs[bk][bn4] = bv;
        __syncthreads();
        #pragma unroll
        for (int k = 0; k < 16; k++) {
            float a0[4];
            *(float4*)a0 = *(const float4*)&As[k][tq << 2];
            ulonglong2 bl = *(const ulonglong2*)&Bs[k][td << 2];
            #pragma unroll
            for (int i = 0; i < 4; i++) {
                unsigned long long ad = dupf(a0[i]);
                FFMA2(acc[i][0], ad, bl.x);
                FFMA2(acc[i][1], ad, bl.y);
            }
        }
    }
    float fm[4][4];
    #pragma unroll
    for (int i = 0; i < 4; i++) {
        unsigned lo, hi;
        asm("mov.b64 {%0, %1}, %2;" : "=r"(lo), "=r"(hi) : "l"(acc[i][0]));
        fm[i][0] = __uint_as_float(lo); fm[i][1] = __uint_as_float(hi);
        asm("mov.b64 {%0, %1}, %2;" : "=r"(lo), "=r"(hi) : "l"(acc[i][1]));
        fm[i][2] = __uint_as_float(lo); fm[i][3] = __uint_as_float(hi);
    }
    const int b  = m0 >> 11;
    const int nn = m0 & (N_ - 1);
    const int bh = b * H_ + (n0 >> 6);

    float* bp = g_hT + (bh * D_ + td * 4) * N_ + nn + tq * 4;
    #pragma unroll
    for (int dd = 0; dd < 4; dd++)
        *(float4*)(bp + dd * N_) = make_float4(fm[0][dd], fm[1][dd], fm[2][dd], fm[3][dd]);

    {
        float sa4[4], sd4[4];
        #pragma unroll
        for (int dd = 0; dd < 4; dd++) {
            sa4[dd] = a_src[n0 + td * 4 + dd];
            sd4[dd] = a_dst[n0 + td * 4 + dd];
        }
        #pragma unroll
        for (int i = 0; i < 4; i++) {
            float ps = 0.f, pd = 0.f;
            #pragma unroll
            for (int dd = 0; dd < 4; dd++) {
                ps = fmaf(fm[i][dd], sa4[dd], ps);
                pd = fmaf(fm[i][dd], sd4[dd], pd);
            }
            redS[tq * 4 + i][td] = ps;
            redD[tq * 4 + i][td] = pd;
        }
    }
    __syncthreads();
    if (t < 64) {
        float s = 0.f, d = 0.f;
        #pragma unroll
        for (int j = 0; j < 16; j++) { s += redS[t][j]; d += redD[t][j]; }
        g_srcT[bh * N_ + nn + t] = s;
        g_dstT[bh * N_ + nn + t] = d;
        float mm = d;
        #pragma unroll
        for (int o = 16; o; o >>= 1)
            mm = fmaxf(mm, __shfl_xor_sync(0xffffffffu, mm, o));
        if ((t & 31) == 0) {
            unsigned bits = __float_as_uint(mm);
            unsigned enc  = (mm >= 0.f) ? (bits | 0x80000000u) : ~bits;
            atomicMax(&g_maxdst[bh], enc);
        }
    }
}

// ---------------------------------------------------------------------------
// Kernel 3: attention partials on mma.sync tf32. 128 threads / 4 warps, each
// warp 32 q-rows (TWO A-fragments per B load -> B-LDS traffic halved, 2x ILP).
// blockIdx.z splits the j-range in 2; partial AV+lsum go to g_pout/g_plsum.
// ---------------------------------------------------------------------------
// smem float offsets
#define KT0_F   0                      // 64 x 68
#define KT1_F   4352
#define SDST_F  8704                   // 2 x 64
#define SBM_F   8832                   // 2 x 256 (unsigned)
#define SRC_F   9344                   // 128
#define CL_F    9472                   // 128
#define SM_TOTF 9600                   // floats = 38400 B
#define KT_DB   17408                  // byte delta between Kt buffers

__global__ __launch_bounds__(128, 4) void k_attn() {
    extern __shared__ float sm[];
    float*    sDst = sm + SDST_F;
    unsigned* sBm  = (unsigned*)(sm + SBM_F);
    float*    sSrc = sm + SRC_F;
    float*    sCl  = sm + CL_F;

    const int t    = threadIdx.x;
    const int w    = t >> 5, lane = t & 31;
    const int qt0  = blockIdx.x * QTILE;
    const int bh   = blockIdx.y;
    const int jr   = blockIdx.z;
    const int jbase = jr * JRANGE;

    unsigned enc = g_maxdst[bh];
    float mdst = (enc & 0x80000000u) ? __uint_as_float(enc & 0x7fffffffu)
                                     : __uint_as_float(~enc);
    {
        float s = g_srcT[bh * N_ + qt0 + t];
        sSrc[t] = s;
        float l = s + mdst;
        float C = fmaxf(l, NEG_SLOPE * l);
        sCl[t] = C * LOG2E;
    }

    // ---- Kt staging: kd = t&63 (conflict-free STS.128), 32 floats/thread ----
    const int kd   = t & 63;
    const int kj   = (t >> 6) << 5;
    const int krow_off = kd * 68 + kj;
    const float* ksrc0 = g_hT + (bh * D_ + kd) * N_ + kj + jbase;

    // ---- fragment lane mapping: warp owns q rows w*32..+31, frags f=0,1 ----
    const int g  = lane >> 2;
    const int lc = lane & 3;
    const int qr0 = w * 32 + g;       // frag0 rows: qr0, qr0+8
    const int qr1 = qr0 + 16;         // frag1 rows: qr1, qr1+8

    // ---- ldmatrix B lane addresses (byte, buffer 0) ----
    const uint32_t smb = smem_u32(sm);
    const int lm = lane >> 3, lr = lane & 7;
    uint32_t baddr0[4];
    #pragma unroll
    for (int p = 0; p < 4; p++) {
        int nt = p + ((lm >> 1) << 2);
        baddr0[p] = smb + (uint32_t)((KT0_F + (nt * 8 + lr) * 68
                                      + ((lm & 1) << 2)) << 2);
    }

    __syncthreads();
    const float sva0 = sSrc[qr0],     Cla0 = sCl[qr0];
    const float svb0 = sSrc[qr0 + 8], Clb0 = sCl[qr0 + 8];
    const float sva1 = sSrc[qr1],     Cla1 = sCl[qr1];
    const float svb1 = sSrc[qr1 + 8], Clb1 = sCl[qr1 + 8];

    float acc[2][8][4];
    #pragma unroll
    for (int f = 0; f < 2; f++)
        #pragma unroll
        for (int n = 0; n < 8; n++)
            #pragma unroll
            for (int i = 0; i < 4; i++) acc[f][n][i] = 0.f;
    float lsA0 = 0.f, lsB0 = 0.f, lsA1 = 0.f, lsB1 = 0.f;

#define STAGE(j0, s)                                                          \
    {                                                                         \
        float* krow = sm + ((s) ? KT1_F : KT0_F) + krow_off;                  \
        const float* ks = ksrc0 + ((j0) - jbase);                             \
        _Pragma("unroll")                                                     \
        for (int i = 0; i < 8; i++)                                           \
            *(float4*)(krow + (i << 2)) = *(const float4*)(ks + (i << 2));    \
        if (t < JT) sDst[(s) * 64 + t] = g_dstT[bh * N_ + (j0) + t];          \
        sBm[(s) * 256 + t]       = g_bm[((j0) >> 5) * N_ + qt0 + t];          \
        sBm[(s) * 256 + 128 + t] = g_bm[(((j0) >> 5) + 1) * N_ + qt0 + t];    \
    }

    STAGE(jbase, 0);

    for (int ch = 0; ch < NCHB; ch++) {
        const int sel = ch & 1;
        __syncthreads();
        if (ch < NCHB - 1) {
            if (sel) STAGE(jbase + (ch + 1) * JT, 0)
            else     STAGE(jbase + (ch + 1) * JT, 1)
        }
        const float*    sD = sDst + sel * 64;
        const unsigned* sB = sBm + sel * 256;
        // pre-shift masks by lc: per-k bit tests become static shifts
        const unsigned long long bmA0 =
            ((((unsigned long long)sB[128 + qr0] << 32) | sB[qr0]) >> lc);
        const unsigned long long bmB0 =
            ((((unsigned long long)sB[128 + qr0 + 8] << 32) | sB[qr0 + 8]) >> lc);
        const unsigned long long bmA1 =
            ((((unsigned long long)sB[128 + qr1] << 32) | sB[qr1]) >> lc);
        const unsigned long long bmB1 =
            ((((unsigned long long)sB[128 + qr1 + 8] << 32) | sB[qr1 + 8]) >> lc);
        const uint32_t bdlt = (uint32_t)(sel * KT_DB);

        #pragma unroll
        for (int k = 0; k < 8; k++) {
            const int j1 = (k << 3) + lc;
            const int j2 = j1 + 4;
            float d1 = sD[j1], d2 = sD[j2];
            // frag 0
            float l0 = sva0 + d1, l1 = svb0 + d1, l2 = sva0 + d2, l3 = svb0 + d2;
            l0 = fmaxf(l0, NEG_SLOPE * l0);
            l1 = fmaxf(l1, NEG_SLOPE * l1);
            l2 = fmaxf(l2, NEG_SLOPE * l2);
            l3 = fmaxf(l3, NEG_SLOPE * l3);
            float e0 = ex2f(fmaf(l0, LOG2E, -Cla0));
            float e1 = ex2f(fmaf(l1, LOG2E, -Clb0));
            float e2 = ex2f(fmaf(l2, LOG2E, -Cla0));
            float e3 = ex2f(fmaf(l3, LOG2E, -Clb0));
            e0 = ((bmA0 >> (k << 3)) & 1ull) ? e0 : 0.f;
            e1 = ((bmB0 >> (k << 3)) & 1ull) ? e1 : 0.f;
            e2 = ((bmA0 >> ((k << 3) + 4)) & 1ull) ? e2 : 0.f;
            e3 = ((bmB0 >> ((k << 3) + 4)) & 1ull) ? e3 : 0.f;
            lsA0 += e0 + e2; lsB0 += e1 + e3;
            // frag 1
            float m0 = sva1 + d1, m1 = svb1 + d1, m2 = sva1 + d2, m3 = svb1 + d2;
            m0 = fmaxf(m0, NEG_SLOPE * m0);
            m1 = fmaxf(m1, NEG_SLOPE * m1);
            m2 = fmaxf(m2, NEG_SLOPE * m2);
            m3 = fmaxf(m3, NEG_SLOPE * m3);
            float f0 = ex2f(fmaf(m0, LOG2E, -Cla1));
            float f1 = ex2f(fmaf(m1, LOG2E, -Clb1));
            float f2 = ex2f(fmaf(m2, LOG2E, -Cla1));
            float f3 = ex2f(fmaf(m3, LOG2E, -Clb1));
            f0 = ((bmA1 >> (k << 3)) & 1ull) ? f0 : 0.f;
            f1 = ((bmB1 >> (k << 3)) & 1ull) ? f1 : 0.f;
            f2 = ((bmA1 >> ((k << 3) + 4)) & 1ull) ? f2 : 0.f;
            f3 = ((bmB1 >> ((k << 3) + 4)) & 1ull) ? f3 : 0.f;
            lsA1 += f0 + f2; lsB1 += f1 + f3;

            const uint32_t a0 = __float_as_uint(e0), a1 = __float_as_uint(e1);
            const uint32_t a2 = __float_as_uint(e2), a3 = __float_as_uint(e3);
            const uint32_t c0 = __float_as_uint(f0), c1 = __float_as_uint(f1);
            const uint32_t c2 = __float_as_uint(f2), c3 = __float_as_uint(f3);
            #pragma unroll
            for (int p = 0; p < 4; p++) {
                uint32_t b0, b1, b2, b3;
                LDSM4(b0, b1, b2, b3, baddr0[p] + bdlt + (k << 5));
                MMA_TF32(acc[0][p][0], acc[0][p][1], acc[0][p][2], acc[0][p][3],
                         a0, a1, a2, a3, b0, b1);
                MMA_TF32(acc[0][p+4][0], acc[0][p+4][1], acc[0][p+4][2], acc[0][p+4][3],
                         a0, a1, a2, a3, b2, b3);
                MMA_TF32(acc[1][p][0], acc[1][p][1], acc[1][p][2], acc[1][p][3],
                         c0, c1, c2, c3, b0, b1);
                MMA_TF32(acc[1][p+4][0], acc[1][p+4][1], acc[1][p+4][2], acc[1][p+4][3],
                         c0, c1, c2, c3, b2, b3);
            }
        }
    }
#undef STAGE

    // ---- lsum reduce over lc quad; write partial sums ----
    lsA0 += __shfl_xor_sync(0xffffffffu, lsA0, 1);
    lsA0 += __shfl_xor_sync(0xffffffffu, lsA0, 2);
    lsB0 += __shfl_xor_sync(0xffffffffu, lsB0, 1);
    lsB0 += __shfl_xor_sync(0xffffffffu, lsB0, 2);
    lsA1 += __shfl_xor_sync(0xffffffffu, lsA1, 1);
    lsA1 += __shfl_xor_sync(0xffffffffu, lsA1, 2);
    lsB1 += __shfl_xor_sync(0xffffffffu, lsB1, 1);
    lsB1 += __shfl_xor_sync(0xffffffffu, lsB1, 2);
    const int ngbase = (jr * 16 + bh) * N_ + qt0;
    if (lc == 0) {
        g_plsum[ngbase + qr0]      = lsA0;
        g_plsum[ngbase + qr0 + 8]  = lsB0;
        g_plsum[ngbase + qr1]      = lsA1;
        g_plsum[ngbase + qr1 + 8]  = lsB1;
    }

    // ---- write unnormalized partial AV ----
    #pragma unroll
    for (int f = 0; f < 2; f++) {
        const int ra = (f ? qr1 : qr0);
        float* pa = g_pout + (size_t)(ngbase + ra) * D_ + lc * 2;
        float* pb = g_pout + (size_t)(ngbase + ra + 8) * D_ + lc * 2;
        #pragma unroll
        for (int nt = 0; nt < 8; nt++) {
            *(float2*)(pa + nt * 8) = make_float2(acc[f][nt][0], acc[f][nt][1]);
            *(float2*)(pb + nt * 8) = make_float2(acc[f][nt][2], acc[f][nt][3]);
        }
    }
}

// ---------------------------------------------------------------------------
// Kernel 4: combine the two j-split partials, normalize, ELU, store.
// ---------------------------------------------------------------------------
__global__ __launch_bounds__(256) void k_comb(float* __restrict__ out) {
    const int gid = blockIdx.x * 256 + threadIdx.x;   // 0 .. 512K-1 (float4 units)
    const int d4 = gid & 15;
    const int ng = gid >> 4;                           // bh*N_ + n
    const int bh = ng >> 11, n = ng & (N_ - 1);
    const int b = bh >> 2, hh = bh & 3;
    float4 p0 = *(const float4*)(g_pout + (size_t)ng * D_ + d4 * 4);
    float4 p1 = *(const float4*)(g_pout + (size_t)(16 * N_ + ng) * D_ + d4 * 4);
    float inv = 1.f / (g_plsum[ng] + g_plsum[16 * N_ + ng]);
    float v0 = (p0.x + p1.x) * inv;
    float v1 = (p0.y + p1.y) * inv;
    float v2 = (p0.z + p1.z) * inv;
    float v3 = (p0.w + p1.w) * inv;
    v0 = (v0 > 0.f) ? v0 : expm1f(v0);
    v1 = (v1 > 0.f) ? v1 : expm1f(v1);
    v2 = (v2 > 0.f) ? v2 : expm1f(v2);
    v3 = (v3 > 0.f) ? v3 : expm1f(v3);
    *(float4*)(out + (size_t)(b * N_ + n) * HD_ + hh * D_ + d4 * 4) =
        make_float4(v0, v1, v2, v3);
}

// ---------------------------------------------------------------------------
extern "C" void kernel_launch(void* const* d_in, const int* in_sizes, int n_in,
                              void* d_out, int out_size) {
    const float* x      = (const float*)d_in[0];
    const int*   A_mask = (const int*)d_in[1];
    const float* W      = (const float*)d_in[2];
    const float* a_src  = (const float*)d_in[3];
    const float* a_dst  = (const float*)d_in[4];
    float* out = (float*)d_out;

    cudaFuncSetAttribute(k_attn, cudaFuncAttributeMaxDynamicSharedMemorySize,
                         SM_TOTF * (int)sizeof(float));

    k_init<<<1, 32>>>();
    k_bitpack<<<(N_ * NW) / 256, 256>>>(A_mask);
    k_gemm<<<dim3(M_ / 64, HD_ / 64), 256>>>(x, W, a_src, a_dst);
    k_attn<<<dim3(N_ / QTILE, B_ * H_, JSPLIT), 128,
             SM_TOTF * (int)sizeof(float)>>>();
    k_comb<<<(B_ * H_ * N_ * D_) / (4 * 256), 256>>>(out);
}

// round 11
// speedup vs baseline: 1.1498x; 1.0146x over previous
#include <cuda_runtime.h>
#include <cstdint>

#define B_ 4
#define N_ 2048
#define IND_ 256
#define H_ 4
#define D_ 64
#define HD_ 256
#define M_ (B_*N_)
#define NEG_SLOPE 0.2f
#define LOG2E 1.4426950408889634f

#define QTILE 128
#define JT 64
#define JSPLIT 4
#define JRANGE (N_/JSPLIT)          // 512 j per block
#define NCHB (JRANGE/JT)            // 8 chunks per block
#define NW (N_/32)                  // bitmask words per row = 64

// Scratch (static __device__ arrays; no allocation allowed)
__device__ float g_hT[B_*H_*D_*N_];    // [bh][d][n], 8 MB
__device__ float g_srcT[B_*H_*N_];     // [bh][n]
__device__ float g_dstT[B_*H_*N_];
__device__ unsigned g_bm[NW*N_];       // bit-packed mask TRANSPOSED [w][q]
__device__ unsigned g_maxdst[B_*H_];
__device__ float g_pout[JSPLIT*B_*H_*N_*D_];   // 32 MB partial AV
__device__ float g_plsum[JSPLIT*B_*H_*N_];     // partial lsum
__device__ unsigned g_ticket[(N_/QTILE)*B_*H_]; // 256 split-k tickets

// ---------------------------------------------------------------------------
// helpers
// ---------------------------------------------------------------------------
__device__ __forceinline__ float ex2f(float x) {
    float r; asm("ex2.approx.f32 %0, %1;" : "=f"(r) : "f"(x)); return r;
}
__device__ __forceinline__ unsigned long long dupf(float v) {
    unsigned long long r;
    unsigned u = __float_as_uint(v);
    asm("mov.b64 %0, {%1, %1};" : "=l"(r) : "r"(u));
    return r;
}
#define FFMA2(d, a, b) asm("fma.rn.f32x2 %0, %1, %2, %0;" : "+l"(d) : "l"(a), "l"(b))

__device__ __forceinline__ uint32_t smem_u32(const void* p) {
    uint32_t a;
    asm("{ .reg .u64 tmp; cvta.to.shared.u64 tmp, %1; cvt.u32.u64 %0, tmp; }"
        : "=r"(a) : "l"(p));
    return a;
}
#define LDSM4(r0, r1, r2, r3, addr) \
    asm volatile("ldmatrix.sync.aligned.m8n8.x4.shared.b16 {%0,%1,%2,%3}, [%4];" \
                 : "=r"(r0), "=r"(r1), "=r"(r2), "=r"(r3) : "r"(addr))
#define MMA_TF32(d0, d1, d2, d3, a0, a1, a2, a3, b0, b1) \
    asm volatile("mma.sync.aligned.m16n8k8.row.col.f32.tf32.tf32.f32 " \
                 "{%0,%1,%2,%3}, {%4,%5,%6,%7}, {%8,%9}, {%0,%1,%2,%3};" \
                 : "+f"(d0), "+f"(d1), "+f"(d2), "+f"(d3) \
                 : "r"(a0), "r"(a1), "r"(a2), "r"(a3), "r"(b0), "r"(b1))

// ---------------------------------------------------------------------------
// Kernel: bit-pack mask (transposed) + reset maxdst/tickets (block 0)
// ---------------------------------------------------------------------------
__global__ __launch_bounds__(256) void k_bitpack(const int* __restrict__ A_mask) {
    if (blockIdx.x == 0) {
        if (threadIdx.x < B_*H_) g_maxdst[threadIdx.x] = 0u;
        g_ticket[threadIdx.x] = 0u;
    }
    int tid = blockIdx.x * 256 + threadIdx.x;
    int q = tid & (N_ - 1);
    int w = tid >> 11;
    const int4* p = (const int4*)(A_mask + q * N_ + w * 32);
    unsigned bits = 0;
    #pragma unroll
    for (int i = 0; i < 8; i++) {
        int4 m = p[i];
        bits |= (unsigned)(m.x != 0) << (4*i)
             |  (unsigned)(m.y != 0) << (4*i+1)
             |  (unsigned)(m.z != 0) << (4*i+2)
             |  (unsigned)(m.w != 0) << (4*i+3);
    }
    g_bm[w * N_ + q] = bits;
}

// ---------------------------------------------------------------------------
// Kernel 1: h = x @ W, FFMA2; epilogue writes TRANSPOSED g_hT + fused src/dst
// ---------------------------------------------------------------------------
__global__ __launch_bounds__(256) void k_gemm(const float* __restrict__ x,
                                              const float* __restrict__ W,
                                              const float* __restrict__ a_src,
                                              const float* __restrict__ a_dst) {
    __shared__ float As[16][68];
    __shared__ float Bs[16][68];
    __shared__ float redS[64][17];
    __shared__ float redD[64][17];
    const int t  = threadIdx.x;
    const int m0 = blockIdx.x * 64;
    const int n0 = blockIdx.y * 64;
    const int tq = t >> 4, td = t & 15;
    const int am = t >> 2, ak4 = (t & 3) << 2;
    const int bk = t >> 4, bn4 = (t & 15) << 2;

    unsigned long long acc[4][2];
    #pragma unroll
    for (int i = 0; i < 4; i++) { acc[i][0] = 0ull; acc[i][1] = 0ull; }

    for (int k0 = 0; k0 < IND_; k0 += 16) {
        float4 av = *(const float4*)(x + (m0 + am) * IND_ + k0 + ak4);
        float4 bv = *(const float4*)(W + (k0 + bk) * HD_ + n0 + bn4);
        __syncthreads();
        As[ak4 + 0][am] = av.x;
        As[ak4 + 1][am] = av.y;
        As[ak4 + 2][am] = av.z;
        As[ak4 + 3][am] = av.w;
        *(float4*)&Bs[bk][bn4] = bv;
        __syncthreads();
        #pragma unroll
        for (int k = 0; k < 16; k++) {
            float a0[4];
            *(float4*)a0 = *(const float4*)&As[k][tq << 2];
            ulonglong2 bl = *(const ulonglong2*)&Bs[k][td << 2];
            #pragma unroll
            for (int i = 0; i < 4; i++) {
                unsigned long long ad = dupf(a0[i]);
                FFMA2(acc[i][0], ad, bl.x);
                FFMA2(acc[i][1], ad, bl.y);
            }
        }
    }
    float fm[4][4];
    #pragma unroll
    for (int i = 0; i < 4; i++) {
        unsigned lo, hi;
        asm("mov.b64 {%0, %1}, %2;" : "=r"(lo), "=r"(hi) : "l"(acc[i][0]));
        fm[i][0] = __uint_as_float(lo); fm[i][1] = __uint_as_float(hi);
        asm("mov.b64 {%0, %1}, %2;" : "=r"(lo), "=r"(hi) : "l"(acc[i][1]));
        fm[i][2] = __uint_as_float(lo); fm[i][3] = __uint_as_float(hi);
    }
    const int b  = m0 >> 11;
    const int nn = m0 & (N_ - 1);
    const int bh = b * H_ + (n0 >> 6);

    float* bp = g_hT + (bh * D_ + td * 4) * N_ + nn + tq * 4;
    #pragma unroll
    for (int dd = 0; dd < 4; dd++)
        *(float4*)(bp + dd * N_) = make_float4(fm[0][dd], fm[1][dd], fm[2][dd], fm[3][dd]);

    {
        float sa4[4], sd4[4];
        #pragma unroll
        for (int dd = 0; dd < 4; dd++) {
            sa4[dd] = a_src[n0 + td * 4 + dd];
            sd4[dd] = a_dst[n0 + td * 4 + dd];
        }
        #pragma unroll
        for (int i = 0; i < 4; i++) {
            float ps = 0.f, pd = 0.f;
            #pragma unroll
            for (int dd = 0; dd < 4; dd++) {
                ps = fmaf(fm[i][dd], sa4[dd], ps);
                pd = fmaf(fm[i][dd], sd4[dd], pd);
            }
            redS[tq * 4 + i][td] = ps;
            redD[tq * 4 + i][td] = pd;
        }
    }
    __syncthreads();
    if (t < 64) {
        float s = 0.f, d = 0.f;
        #pragma unroll
        for (int j = 0; j < 16; j++) { s += redS[t][j]; d += redD[t][j]; }
        g_srcT[bh * N_ + nn + t] = s;
        g_dstT[bh * N_ + nn + t] = d;
        float mm = d;
        #pragma unroll
        for (int o = 16; o; o >>= 1)
            mm = fmaxf(mm, __shfl_xor_sync(0xffffffffu, mm, o));
        if ((t & 31) == 0) {
            unsigned bits = __float_as_uint(mm);
            unsigned enc  = (mm >= 0.f) ? (bits | 0x80000000u) : ~bits;
            atomicMax(&g_maxdst[bh], enc);
        }
    }
}

// ---------------------------------------------------------------------------
// Kernel 3: attention partials on mma.sync tf32; 4 warps x 32 q-rows.
// blockIdx.z = j-split (4). Last-arriving block per (qtile,bh) combines the
// partials (ticket pattern), normalizes, ELUs, stores — no separate kernel.
// ---------------------------------------------------------------------------
// smem float offsets
#define KT0_F   0                      // 64 x 68
#define KT1_F   4352
#define SDST_F  8704                   // 2 x 64
#define SBM_F   8832                   // 2 x 256 (unsigned)
#define SRC_F   9344                   // 128
#define CL_F    9472                   // 128
#define SM_TOTF 9600                   // floats = 38400 B
#define KT_DB   17408                  // byte delta between Kt buffers

__global__ __launch_bounds__(128, 4) void k_attn(float* __restrict__ out) {
    extern __shared__ float sm[];
    float*    sDst = sm + SDST_F;
    unsigned* sBm  = (unsigned*)(sm + SBM_F);
    float*    sSrc = sm + SRC_F;
    float*    sCl  = sm + CL_F;

    const int t    = threadIdx.x;
    const int w    = t >> 5, lane = t & 31;
    const int qt0  = blockIdx.x * QTILE;
    const int bh   = blockIdx.y;
    const int jr   = blockIdx.z;
    const int jbase = jr * JRANGE;

    unsigned enc = g_maxdst[bh];
    float mdst = (enc & 0x80000000u) ? __uint_as_float(enc & 0x7fffffffu)
                                     : __uint_as_float(~enc);
    {
        float s = g_srcT[bh * N_ + qt0 + t];
        sSrc[t] = s;
        float l = s + mdst;
        float C = fmaxf(l, NEG_SLOPE * l);
        sCl[t] = C * LOG2E;
    }

    // ---- Kt staging: kd = t&63 (conflict-free STS.128), 32 floats/thread ----
    const int kd   = t & 63;
    const int kj   = (t >> 6) << 5;
    const int krow_off = kd * 68 + kj;
    const float* ksrc0 = g_hT + (bh * D_ + kd) * N_ + kj + jbase;

    // ---- fragment lane mapping: warp owns q rows w*32..+31, frags f=0,1 ----
    const int g  = lane >> 2;
    const int lc = lane & 3;
    const int qr0 = w * 32 + g;
    const int qr1 = qr0 + 16;

    // ---- ldmatrix B lane addresses (byte, buffer 0) ----
    const uint32_t smb = smem_u32(sm);
    const int lm = lane >> 3, lr = lane & 7;
    uint32_t baddr0[4];
    #pragma unroll
    for (int p = 0; p < 4; p++) {
        int nt = p + ((lm >> 1) << 2);
        baddr0[p] = smb + (uint32_t)((KT0_F + (nt * 8 + lr) * 68
                                      + ((lm & 1) << 2)) << 2);
    }

    __syncthreads();
    const float sva0 = sSrc[qr0],     Cla0 = sCl[qr0];
    const float svb0 = sSrc[qr0 + 8], Clb0 = sCl[qr0 + 8];
    const float sva1 = sSrc[qr1],     Cla1 = sCl[qr1];
    const float svb1 = sSrc[qr1 + 8], Clb1 = sCl[qr1 + 8];

    float acc[2][8][4];
    #pragma unroll
    for (int f = 0; f < 2; f++)
        #pragma unroll
        for (int n = 0; n < 8; n++)
            #pragma unroll
            for (int i = 0; i < 4; i++) acc[f][n][i] = 0.f;
    float lsA0 = 0.f, lsB0 = 0.f, lsA1 = 0.f, lsB1 = 0.f;

#define STAGE(j0, s)                                                          \
    {                                                                         \
        float* krow = sm + ((s) ? KT1_F : KT0_F) + krow_off;                  \
        const float* ks = ksrc0 + ((j0) - jbase);                             \
        _Pragma("unroll")                                                     \
        for (int i = 0; i < 8; i++)                                           \
            *(float4*)(krow + (i << 2)) = *(const float4*)(ks + (i << 2));    \
        if (t < JT) sDst[(s) * 64 + t] = g_dstT[bh * N_ + (j0) + t];          \
        sBm[(s) * 256 + t]       = g_bm[((j0) >> 5) * N_ + qt0 + t];          \
        sBm[(s) * 256 + 128 + t] = g_bm[(((j0) >> 5) + 1) * N_ + qt0 + t];    \
    }

    STAGE(jbase, 0);

    for (int ch = 0; ch < NCHB; ch++) {
        const int sel = ch & 1;
        __syncthreads();
        if (ch < NCHB - 1) {
            if (sel) STAGE(jbase + (ch + 1) * JT, 0)
            else     STAGE(jbase + (ch + 1) * JT, 1)
        }
        const float*    sD = sDst + sel * 64;
        const unsigned* sB = sBm + sel * 256;
        const unsigned long long bmA0 =
            ((((unsigned long long)sB[128 + qr0] << 32) | sB[qr0]) >> lc);
        const unsigned long long bmB0 =
            ((((unsigned long long)sB[128 + qr0 + 8] << 32) | sB[qr0 + 8]) >> lc);
        const unsigned long long bmA1 =
            ((((unsigned long long)sB[128 + qr1] << 32) | sB[qr1]) >> lc);
        const unsigned long long bmB1 =
            ((((unsigned long long)sB[128 + qr1 + 8] << 32) | sB[qr1 + 8]) >> lc);
        const uint32_t bdlt = (uint32_t)(sel * KT_DB);

        #pragma unroll
        for (int k = 0; k < 8; k++) {
            const int j1 = (k << 3) + lc;
            const int j2 = j1 + 4;
            float d1 = sD[j1], d2 = sD[j2];
            // frag 0
            float l0 = sva0 + d1, l1 = svb0 + d1, l2 = sva0 + d2, l3 = svb0 + d2;
            l0 = fmaxf(l0, NEG_SLOPE * l0);
            l1 = fmaxf(l1, NEG_SLOPE * l1);
            l2 = fmaxf(l2, NEG_SLOPE * l2);
            l3 = fmaxf(l3, NEG_SLOPE * l3);
            float e0 = ex2f(fmaf(l0, LOG2E, -Cla0));
            float e1 = ex2f(fmaf(l1, LOG2E, -Clb0));
            float e2 = ex2f(fmaf(l2, LOG2E, -Cla0));
            float e3 = ex2f(fmaf(l3, LOG2E, -Clb0));
            e0 = ((bmA0 >> (k << 3)) & 1ull) ? e0 : 0.f;
            e1 = ((bmB0 >> (k << 3)) & 1ull) ? e1 : 0.f;
            e2 = ((bmA0 >> ((k << 3) + 4)) & 1ull) ? e2 : 0.f;
            e3 = ((bmB0 >> ((k << 3) + 4)) & 1ull) ? e3 : 0.f;
            lsA0 += e0 + e2; lsB0 += e1 + e3;
            // frag 1
            float m0 = sva1 + d1, m1 = svb1 + d1, m2 = sva1 + d2, m3 = svb1 + d2;
            m0 = fmaxf(m0, NEG_SLOPE * m0);
            m1 = fmaxf(m1, NEG_SLOPE * m1);
            m2 = fmaxf(m2, NEG_SLOPE * m2);
            m3 = fmaxf(m3, NEG_SLOPE * m3);
            float f0 = ex2f(fmaf(m0, LOG2E, -Cla1));
            float f1 = ex2f(fmaf(m1, LOG2E, -Clb1));
            float f2 = ex2f(fmaf(m2, LOG2E, -Cla1));
            float f3 = ex2f(fmaf(m3, LOG2E, -Clb1));
            f0 = ((bmA1 >> (k << 3)) & 1ull) ? f0 : 0.f;
            f1 = ((bmB1 >> (k << 3)) & 1ull) ? f1 : 0.f;
            f2 = ((bmA1 >> ((k << 3) + 4)) & 1ull) ? f2 : 0.f;
            f3 = ((bmB1 >> ((k << 3) + 4)) & 1ull) ? f3 : 0.f;
            lsA1 += f0 + f2; lsB1 += f1 + f3;

            const uint32_t a0 = __float_as_uint(e0), a1 = __float_as_uint(e1);
            const uint32_t a2 = __float_as_uint(e2), a3 = __float_as_uint(e3);
            const uint32_t c0 = __float_as_uint(f0), c1 = __float_as_uint(f1);
            const uint32_t c2 = __float_as_uint(f2), c3 = __float_as_uint(f3);
            #pragma unroll
            for (int p = 0; p < 4; p++) {
                uint32_t b0, b1, b2, b3;
                LDSM4(b0, b1, b2, b3, baddr0[p] + bdlt + (k << 5));
                MMA_TF32(acc[0][p][0], acc[0][p][1], acc[0][p][2], acc[0][p][3],
                         a0, a1, a2, a3, b0, b1);
                MMA_TF32(acc[0][p+4][0], acc[0][p+4][1], acc[0][p+4][2], acc[0][p+4][3],
                         a0, a1, a2, a3, b2, b3);
                MMA_TF32(acc[1][p][0], acc[1][p][1], acc[1][p][2], acc[1][p][3],
                         c0, c1, c2, c3, b0, b1);
                MMA_TF32(acc[1][p+4][0], acc[1][p+4][1], acc[1][p+4][2], acc[1][p+4][3],
                         c0, c1, c2, c3, b2, b3);
            }
        }
    }
#undef STAGE

    // ---- lsum reduce over lc quad; write partial sums ----
    lsA0 += __shfl_xor_sync(0xffffffffu, lsA0, 1);
    lsA0 += __shfl_xor_sync(0xffffffffu, lsA0, 2);
    lsB0 += __shfl_xor_sync(0xffffffffu, lsB0, 1);
    lsB0 += __shfl_xor_sync(0xffffffffu, lsB0, 2);
    lsA1 += __shfl_xor_sync(0xffffffffu, lsA1, 1);
    lsA1 += __shfl_xor_sync(0xffffffffu, lsA1, 2);
    lsB1 += __shfl_xor_sync(0xffffffffu, lsB1, 1);
    lsB1 += __shfl_xor_sync(0xffffffffu, lsB1, 2);
    const int ngbase = (jr * (B_ * H_) + bh) * N_ + qt0;
    if (lc == 0) {
        g_plsum[ngbase + qr0]      = lsA0;
        g_plsum[ngbase + qr0 + 8]  = lsB0;
        g_plsum[ngbase + qr1]      = lsA1;
        g_plsum[ngbase + qr1 + 8]  = lsB1;
    }

    // ---- write unnormalized partial AV ----
    #pragma unroll
    for (int f = 0; f < 2; f++) {
        const int ra = (f ? qr1 : qr0);
        float* pa = g_pout + (size_t)(ngbase + ra) * D_ + lc * 2;
        float* pb = g_pout + (size_t)(ngbase + ra + 8) * D_ + lc * 2;
        #pragma unroll
        for (int nt = 0; nt < 8; nt++) {
            *(float2*)(pa + nt * 8) = make_float2(acc[f][nt][0], acc[f][nt][1]);
            *(float2*)(pb + nt * 8) = make_float2(acc[f][nt][2], acc[f][nt][3]);
        }
    }

    // ---- split-k combine: last-arriving block of this (qtile,bh) ----
    __threadfence();
    __syncthreads();
    __shared__ unsigned s_last;
    if (t == 0) {
        unsigned old = atomicAdd(&g_ticket[blockIdx.x * (B_ * H_) + bh], 1u);
        s_last = (old == JSPLIT - 1) ? 1u : 0u;
    }
    __syncthreads();
    if (s_last) {
        const int d4  = t & 15;      // float4 lane within 64-d row (coalesced)
        const int qb0 = t >> 4;      // 0..7
        const int b2  = bh >> 2, hh2 = bh & 3;
        #pragma unroll
        for (int pass = 0; pass < 16; pass++) {
            const int q  = qb0 + pass * 8;
            const int ng = bh * N_ + qt0 + q;
            float ls = 0.f;
            float4 s4 = make_float4(0.f, 0.f, 0.f, 0.f);
            #pragma unroll
            for (int p = 0; p < JSPLIT; p++) {
                const int pg = p * (B_ * H_) * N_ + ng;
                ls += g_plsum[pg];
                float4 v = *(const float4*)(g_pout + (size_t)pg * D_ + d4 * 4);
                s4.x += v.x; s4.y += v.y; s4.z += v.z; s4.w += v.w;
            }
            const float inv = 1.f / ls;
            float v0 = s4.x * inv, v1 = s4.y * inv, v2 = s4.z * inv, v3 = s4.w * inv;
            v0 = (v0 > 0.f) ? v0 : expm1f(v0);
            v1 = (v1 > 0.f) ? v1 : expm1f(v1);
            v2 = (v2 > 0.f) ? v2 : expm1f(v2);
            v3 = (v3 > 0.f) ? v3 : expm1f(v3);
            *(float4*)(out + (size_t)(b2 * N_ + qt0 + q) * HD_ + hh2 * D_ + d4 * 4) =
                make_float4(v0, v1, v2, v3);
        }
    }
}

// ---------------------------------------------------------------------------
extern "C" void kernel_launch(void* const* d_in, const int* in_sizes, int n_in,
                              void* d_out, int out_size) {
    const float* x      = (const float*)d_in[0];
    const int*   A_mask = (const int*)d_in[1];
    const float* W      = (const float*)d_in[2];
    const float* a_src  = (const float*)d_in[3];
    const float* a_dst  = (const float*)d_in[4];
    float* out = (float*)d_out;

    cudaFuncSetAttribute(k_attn, cudaFuncAttributeMaxDynamicSharedMemorySize,
                         SM_TOTF * (int)sizeof(float));

    k_bitpack<<<(N_ * NW) / 256, 256>>>(A_mask);
    k_gemm<<<dim3(M_ / 64, HD_ / 64), 256>>>(x, W, a_src, a_dst);
    k_attn<<<dim3(N_ / QTILE, B_ * H_, JSPLIT), 128,
             SM_TOTF * (int)sizeof(float)>>>(out);
}